// round 4
// baseline (speedup 1.0000x reference)
#include <cuda_runtime.h>
#include <cuda_bf16.h>

#define KNN   32
#define MAXC  128          // per-warp candidate cap (Poisson mean ~34, max ~65)
#define NB    50           // z-bins per segment (width = BOX/NB = 1.0)
#define NSEG  8
#define NMAX  8192
#define BOXF  50.0f

__device__ int    g_starts[NSEG + 1];
__device__ float4 g_pq [NMAX];          // original order: (p0,p1,p2,|p|^2)
__device__ float4 g_pqs[NMAX];          // z-bin-sorted within each segment
__device__ int    g_oidx[NMAX];         // sorted position -> original index
__device__ int    g_binstart[NSEG][NB + 1];

// ---------------- Kernel 1: pack pos + x2 (reference rounding), segment bounds
__global__ void prep_kernel(const float* __restrict__ pos,
                            const int* __restrict__ batch, int N) {
    int tid = blockIdx.x * blockDim.x + threadIdx.x;
    int stride = gridDim.x * blockDim.x;
    for (int i = tid; i < N; i += stride) {
        float p0 = pos[3*i+0], p1 = pos[3*i+1], p2 = pos[3*i+2];
        float a = __fadd_rn(__fadd_rn(__fmul_rn(p0,p0), __fmul_rn(p1,p1)),
                            __fmul_rn(p2,p2));
        g_pq[i] = make_float4(p0, p1, p2, a);
    }
    if (blockIdx.x == 0 && threadIdx.x <= NSEG) {
        int b = (int)threadIdx.x;
        int lo = 0, hi = N;
        while (lo < hi) {
            int mid = (lo + hi) >> 1;
            if (batch[mid] < b) lo = mid + 1; else hi = mid;
        }
        g_starts[threadIdx.x] = lo;
    }
}

__device__ __forceinline__ int z_bin(float z) {
    int b = (int)(z * (NB / BOXF));
    return min(NB - 1, max(0, b));
}

// ---------------- Kernel 2: per-segment counting sort by z-bin (8 blocks)
__global__ void __launch_bounds__(1024)
binsort_kernel() {
    __shared__ int s_start[NB];
    __shared__ int s_cursor[NB];
    const int seg = blockIdx.x;
    const int lo = g_starts[seg], hi = g_starts[seg + 1];
    const int n = hi - lo;

    for (int b = threadIdx.x; b < NB; b += blockDim.x) s_cursor[b] = 0;
    __syncthreads();

    // pass 1: histogram
    for (int t = threadIdx.x; t < n; t += blockDim.x) {
        atomicAdd(&s_cursor[z_bin(g_pq[lo + t].z)], 1);
    }
    __syncthreads();

    // exclusive prefix (serial over 50 bins — trivial)
    if (threadIdx.x == 0) {
        int acc = 0;
        for (int b = 0; b < NB; b++) {
            int c = s_cursor[b];
            s_start[b]  = acc;
            s_cursor[b] = acc;
            g_binstart[seg][b] = acc;
            acc += c;
        }
        g_binstart[seg][NB] = acc;
    }
    __syncthreads();

    // pass 2: scatter (order within bin nondeterministic -- output-invariant)
    for (int t = threadIdx.x; t < n; t += blockDim.x) {
        float4 pq = g_pq[lo + t];
        int slot = atomicAdd(&s_cursor[z_bin(pq.z)], 1);
        g_pqs [lo + slot] = pq;
        g_oidx[lo + slot] = lo + t;
    }
}

// Monotonic float->uint (handles tiny negative d2 from gram-trick rounding)
__device__ __forceinline__ unsigned int f2mono(float f) {
    unsigned int u = __float_as_uint(f);
    return (u & 0x80000000u) ? ~u : (u | 0x80000000u);
}

// ---------------- Kernel 3: one WARP per node
__global__ void __launch_bounds__(128)
radius_graph_kernel(const int* __restrict__ batch,
                    float* __restrict__ out, int N) {
    __shared__ unsigned long long s_keys[4][MAXC];
    __shared__ unsigned long long s_sel [4][KNN];

    const int w    = threadIdx.x >> 5;
    const int lane = threadIdx.x & 31;
    const int i    = blockIdx.x * 4 + w;
    if (i >= N) return;                     // no block-level syncs below

    const int b  = batch[i];
    const int lo = g_starts[b];

    const float4 pc = g_pq[i];
    const float p0 = pc.x, p1 = pc.y, p2 = pc.z, x2i = pc.w;

    // z-bin scan range covering [z-10, z+10] (over-covers by <= 1 bin width,
    // which strictly dominates gram-trick rounding slack -> no false prunes)
    const float inv_w = NB / BOXF;
    int bzlo = max(0, (int)floorf((p2 - 10.0f) * inv_w));
    int bzhi = min(NB - 1, (int)floorf((p2 + 10.0f) * inv_w));
    const int rlo = lo + g_binstart[b][bzlo];
    const int rhi = lo + g_binstart[b][bzhi + 1];

    // Phase 1: warp scan + ballot compaction (no atomics)
    int base = 0;
    for (int rb = rlo; rb < rhi; rb += 32) {
        int r  = rb + lane;
        int rc = min(r, rhi - 1);
        float4 q = g_pqs[rc];
        // d2 = (x2i + x2j) - 2*dot, exact reference rounding
        float dot = __fmaf_rn(p2, q.z, __fmaf_rn(p1, q.y, __fmul_rn(p0, q.x)));
        float d2  = __fsub_rn(__fadd_rn(x2i, q.w), __fmul_rn(2.0f, dot));
        bool hitp = (r < rhi) && (d2 <= 100.0f);
        int oid = 0;
        if (hitp) {
            oid  = g_oidx[rc];
            hitp = (oid != i);
        }
        unsigned m = __ballot_sync(0xffffffffu, hitp);
        if (hitp) {
            int slot = base + __popc(m & ((1u << lane) - 1u));
            if (slot < MAXC)
                s_keys[w][slot] = ((unsigned long long)f2mono(d2) << 32)
                                | (unsigned int)oid;
        }
        base += __popc(m);
    }
    const int M = min(base, MAXC);
    __syncwarp();

    // Phase 2: exact rank selection (keys unique; tie -> lower index, = lax.top_k)
    for (int e = lane; e < M; e += 32) {
        unsigned long long mykey = s_keys[w][e];
        int rank = 0;
        for (int t = 0; t < M; t++) rank += (s_keys[w][t] < mykey) ? 1 : 0;
        if (rank < KNN) s_sel[w][rank] = mykey;
    }
    __syncwarp();

    const int Msel = min(M, KNN);
    const long long E = (long long)N * (KNN + 1);

    // Phase 3: lane k writes neighbor slot k (K == warp size)
    {
        const int k = lane;
        long long e = (long long)i * KNN + k;
        float rowf = 0.0f, wgt = 0.0f, mf = 0.0f;
        if (k < Msel) {
            unsigned long long key = s_sel[w][k];
            int j = (int)(key & 0xFFFFFFFFull);
            rowf = (float)j;
            mf   = 1.0f;
            float4 q = g_pq[j];
            float d0  = __fsub_rn(q.x, p0);
            float d1  = __fsub_rn(q.y, p1);
            float d2v = __fsub_rn(q.z, p2);
            float sq = __fadd_rn(__fadd_rn(__fmul_rn(d0,d0), __fmul_rn(d1,d1)),
                                 __fmul_rn(d2v,d2v));
            wgt = (sq > 0.0f) ? __fsqrt_rn(sq) : 0.0f;
        }
        out[e]         = rowf;       // edge_index row
        out[E + e]     = (float)i;   // edge_index col
        out[2*E + e]   = wgt;        // edge_weight (mask applied)
        out[3*E + e]   = mf;         // mask
    }
    if (lane == 0) {                 // self-loop slot N*K + i
        long long se = (long long)N * KNN + i;
        out[se]         = (float)i;
        out[E + se]     = (float)i;
        out[2*E + se]   = 0.0f;
        out[3*E + se]   = 1.0f;
    }
}

extern "C" void kernel_launch(void* const* d_in, const int* in_sizes, int n_in,
                              void* d_out, int out_size) {
    const float* pos   = (const float*)d_in[0];
    const int*   batch = (const int*)d_in[1];
    float*       out   = (float*)d_out;

    int N = in_sizes[0] / 3;   // pos is [N,3] float32

    prep_kernel<<<32, 256>>>(pos, batch, N);
    binsort_kernel<<<NSEG, 1024>>>();
    radius_graph_kernel<<<(N + 3) / 4, 128>>>(batch, out, N);
}

// round 5
// speedup vs baseline: 1.0808x; 1.0808x over previous
#include <cuda_runtime.h>
#include <cuda_bf16.h>

#define KNN   32
#define MAXC  128          // per-warp candidate cap (Poisson mean ~34, max ~65)
#define NB    50           // z-bins per segment (width = BOX/NB = 1.0)
#define NSEG  8
#define NMAX  8192
#define BOXF  50.0f

__device__ int    g_starts[NSEG + 1];
__device__ float4 g_pq [NMAX];          // original order: (p0,p1,p2,|p|^2)
__device__ float4 g_pqs[NMAX];          // z-bin-sorted within each segment
__device__ int    g_oidx[NMAX];         // sorted position -> original index
__device__ int    g_binstart[NSEG][NB + 1];

__device__ __forceinline__ int z_bin(float z) {
    int b = (int)(z * (NB / BOXF));
    return min(NB - 1, max(0, b));
}

// ---------------- Kernel 1 (fused prep + per-segment z-bin counting sort).
// 8 blocks x 1024 threads: each block owns one batch segment. Computes segment
// bounds (redundant per-block binary searches), packs (pos, |p|^2) with the
// reference rounding, histograms z-bins, prefix-sums, scatters.
__global__ void __launch_bounds__(1024)
binsort_kernel(const float* __restrict__ pos,
               const int* __restrict__ batch, int N) {
    __shared__ int s_bounds[NSEG + 1];
    __shared__ int s_cursor[NB];

    const int seg = blockIdx.x;

    // segment bounds: threads 0..NSEG each binary-search one boundary
    if (threadIdx.x <= NSEG) {
        int b = (int)threadIdx.x;
        int lo = 0, hi = N;
        while (lo < hi) {
            int mid = (lo + hi) >> 1;
            if (batch[mid] < b) lo = mid + 1; else hi = mid;
        }
        s_bounds[threadIdx.x] = lo;
        if (seg == 0) g_starts[threadIdx.x] = lo;   // publish once for kernel 2
    }
    if (threadIdx.x < NB) s_cursor[threadIdx.x] = 0;
    __syncthreads();

    const int lo = s_bounds[seg], hi = s_bounds[seg + 1];
    const int n  = hi - lo;

    // pass 1: pack g_pq (reference rounding: (p0*p0 + p1*p1) + p2*p2) + histogram
    for (int t = threadIdx.x; t < n; t += blockDim.x) {
        int i = lo + t;
        float p0 = pos[3*i+0], p1 = pos[3*i+1], p2 = pos[3*i+2];
        float a = __fadd_rn(__fadd_rn(__fmul_rn(p0,p0), __fmul_rn(p1,p1)),
                            __fmul_rn(p2,p2));
        g_pq[i] = make_float4(p0, p1, p2, a);
        atomicAdd(&s_cursor[z_bin(p2)], 1);
    }
    __syncthreads();

    // exclusive prefix over 50 bins (serial -- trivial)
    if (threadIdx.x == 0) {
        int acc = 0;
        for (int b = 0; b < NB; b++) {
            int c = s_cursor[b];
            s_cursor[b] = acc;
            g_binstart[seg][b] = acc;
            acc += c;
        }
        g_binstart[seg][NB] = acc;
    }
    __syncthreads();

    // pass 2: scatter (order within bin nondeterministic -- output-invariant,
    // since selection keys carry the original index)
    for (int t = threadIdx.x; t < n; t += blockDim.x) {
        float4 pq = g_pq[lo + t];
        int slot = atomicAdd(&s_cursor[z_bin(pq.z)], 1);
        g_pqs [lo + slot] = pq;
        g_oidx[lo + slot] = lo + t;
    }
}

// Monotonic float->uint (handles tiny negative d2 from gram-trick rounding)
__device__ __forceinline__ unsigned int f2mono(float f) {
    unsigned int u = __float_as_uint(f);
    return (u & 0x80000000u) ? ~u : (u | 0x80000000u);
}

// ---------------- Kernel 2: one WARP per node
__global__ void __launch_bounds__(128)
radius_graph_kernel(const int* __restrict__ batch,
                    float* __restrict__ out, int N) {
    __shared__ unsigned long long s_keys[4][MAXC];
    __shared__ unsigned long long s_sel [4][KNN];

    const int w    = threadIdx.x >> 5;
    const int lane = threadIdx.x & 31;
    const int i    = blockIdx.x * 4 + w;
    if (i >= N) return;                     // no block-level syncs below

    const int b  = batch[i];
    const int lo = g_starts[b];

    const float4 pc = g_pq[i];
    const float p0 = pc.x, p1 = pc.y, p2 = pc.z, x2i = pc.w;

    // z-bin scan range covering [z-10, z+10] (over-covers by <= 1 bin width,
    // which strictly dominates gram-trick rounding slack -> no false prunes)
    const float inv_w = NB / BOXF;
    int bzlo = max(0, (int)floorf((p2 - 10.0f) * inv_w));
    int bzhi = min(NB - 1, (int)floorf((p2 + 10.0f) * inv_w));
    const int rlo = lo + g_binstart[b][bzlo];
    const int rhi = lo + g_binstart[b][bzhi + 1];

    // Phase 1: warp scan + ballot compaction (no atomics)
    int base = 0;
    for (int rb = rlo; rb < rhi; rb += 32) {
        int r  = rb + lane;
        int rc = min(r, rhi - 1);
        float4 q = g_pqs[rc];
        // d2 = (x2i + x2j) - 2*dot, exact reference rounding
        float dot = __fmaf_rn(p2, q.z, __fmaf_rn(p1, q.y, __fmul_rn(p0, q.x)));
        float d2  = __fsub_rn(__fadd_rn(x2i, q.w), __fmul_rn(2.0f, dot));
        bool hitp = (r < rhi) && (d2 <= 100.0f);
        int oid = 0;
        if (hitp) {
            oid  = g_oidx[rc];
            hitp = (oid != i);
        }
        unsigned m = __ballot_sync(0xffffffffu, hitp);
        if (hitp) {
            int slot = base + __popc(m & ((1u << lane) - 1u));
            if (slot < MAXC)
                s_keys[w][slot] = ((unsigned long long)f2mono(d2) << 32)
                                | (unsigned int)oid;
        }
        base += __popc(m);
    }
    const int M = min(base, MAXC);
    __syncwarp();

    // Phase 2: exact rank selection (keys unique; tie -> lower index, = lax.top_k)
    for (int e = lane; e < M; e += 32) {
        unsigned long long mykey = s_keys[w][e];
        int rank = 0;
        for (int t = 0; t < M; t++) rank += (s_keys[w][t] < mykey) ? 1 : 0;
        if (rank < KNN) s_sel[w][rank] = mykey;
    }
    __syncwarp();

    const int Msel = min(M, KNN);
    const long long E = (long long)N * (KNN + 1);

    // Phase 3: lane k writes neighbor slot k (K == warp size)
    {
        const int k = lane;
        long long e = (long long)i * KNN + k;
        float rowf = 0.0f, wgt = 0.0f, mf = 0.0f;
        if (k < Msel) {
            unsigned long long key = s_sel[w][k];
            int j = (int)(key & 0xFFFFFFFFull);
            rowf = (float)j;
            mf   = 1.0f;
            float4 q = g_pq[j];
            float d0  = __fsub_rn(q.x, p0);
            float d1  = __fsub_rn(q.y, p1);
            float d2v = __fsub_rn(q.z, p2);
            float sq = __fadd_rn(__fadd_rn(__fmul_rn(d0,d0), __fmul_rn(d1,d1)),
                                 __fmul_rn(d2v,d2v));
            wgt = (sq > 0.0f) ? __fsqrt_rn(sq) : 0.0f;
        }
        out[e]         = rowf;       // edge_index row
        out[E + e]     = (float)i;   // edge_index col
        out[2*E + e]   = wgt;        // edge_weight (mask applied)
        out[3*E + e]   = mf;         // mask
    }
    if (lane == 0) {                 // self-loop slot N*K + i
        long long se = (long long)N * KNN + i;
        out[se]         = (float)i;
        out[E + se]     = (float)i;
        out[2*E + se]   = 0.0f;
        out[3*E + se]   = 1.0f;
    }
}

extern "C" void kernel_launch(void* const* d_in, const int* in_sizes, int n_in,
                              void* d_out, int out_size) {
    const float* pos   = (const float*)d_in[0];
    const int*   batch = (const int*)d_in[1];
    float*       out   = (float*)d_out;

    int N = in_sizes[0] / 3;   // pos is [N,3] float32

    binsort_kernel<<<NSEG, 1024>>>(pos, batch, N);
    radius_graph_kernel<<<(N + 3) / 4, 128>>>(batch, out, N);
}